// round 1
// baseline (speedup 1.0000x reference)
#include <cuda_runtime.h>
#include <math.h>
#include <stdint.h>

// Problem constants
#define BB 2
#define SS 512
#define PP 4096
#define TD 512
#define SD 384
#define HH 8
#define HD 64
#define FF 2048
#define NROW_T (BB*SS)   // 1024
#define NROW_S (BB*PP)   // 8192
#define OUT_ELEMS (NROW_T*TD)              // 524288
#define ATTN_ELEMS (BB*HH*SS*PP)           // 33554432

// ---------------- device scratch (no allocations allowed) ----------------
__device__ float g_tn[NROW_T*TD];
__device__ float g_sn[NROW_S*SD];
__device__ float g_q[BB*HH*SS*HD];
__device__ float g_k[BB*HH*PP*HD];
__device__ float g_v[BB*HH*PP*HD];
__device__ float g_m[BB*HH*SS];
__device__ float g_z[BB*HH*SS];
__device__ float g_attnout[NROW_T*TD];
__device__ float g_out1[NROW_T*TD];
__device__ float g_hid[NROW_T*FF];
__device__ float g_tmp[NROW_T*TD];
__device__ float g_shead[HH];

// ---------------- LayerNorm (optionally fused residual add) ----------------
__global__ void ln_kernel(const float* __restrict__ x, const float* __restrict__ add,
                          const float* __restrict__ g, const float* __restrict__ b,
                          float* __restrict__ y, int D) {
    int row = blockIdx.x;
    const float* xr = x + (size_t)row * D;
    const float* ar = add ? add + (size_t)row * D : nullptr;
    float* yr = y + (size_t)row * D;

    float s = 0.f, ss = 0.f;
    for (int i = threadIdx.x; i < D; i += blockDim.x) {
        float v = xr[i] + (ar ? ar[i] : 0.f);
        s += v; ss += v * v;
    }
    __shared__ float sh[66];
    #pragma unroll
    for (int o = 16; o; o >>= 1) {
        s  += __shfl_xor_sync(0xffffffffu, s, o);
        ss += __shfl_xor_sync(0xffffffffu, ss, o);
    }
    int w = threadIdx.x >> 5;
    if ((threadIdx.x & 31) == 0) { sh[w*2] = s; sh[w*2+1] = ss; }
    __syncthreads();
    int nw = blockDim.x >> 5;
    if (threadIdx.x < 32) {
        s  = threadIdx.x < nw ? sh[threadIdx.x*2]   : 0.f;
        ss = threadIdx.x < nw ? sh[threadIdx.x*2+1] : 0.f;
        #pragma unroll
        for (int o = 16; o; o >>= 1) {
            s  += __shfl_xor_sync(0xffffffffu, s, o);
            ss += __shfl_xor_sync(0xffffffffu, ss, o);
        }
        if (threadIdx.x == 0) { sh[64] = s; sh[65] = ss; }
    }
    __syncthreads();
    float mean = sh[64] / (float)D;
    float var  = sh[65] / (float)D - mean * mean;
    float inv  = rsqrtf(var + 1e-5f);
    for (int i = threadIdx.x; i < D; i += blockDim.x) {
        float v = xr[i] + (ar ? ar[i] : 0.f);
        yr[i] = (v - mean) * inv * g[i] + b[i];
    }
}

// ---------------- per-head edge scalar: s[h] = edge_emb[h,:] . ep_w ----------------
__global__ void edge_scalar_kernel(const float* __restrict__ emb, const float* __restrict__ w,
                                   float* __restrict__ s) {
    int h = threadIdx.x;
    if (h < HH) {
        float acc = 0.f;
        #pragma unroll
        for (int e = 0; e < 32; e++) acc += emb[h*32 + e] * w[e];
        s[h] = acc;
    }
}

// ---------------- generic 64x64 tiled SGEMM: C = A[MxK] * W[KxN] + bias ----------------
// MODE 0: plain row-major store.  MODE 1: head-scatter to [b,h,t,d] (T tokens/batch).
// MODE 2: exact GELU epilogue.
template<int MODE>
__global__ void sgemm64(const float* __restrict__ A, const float* __restrict__ W,
                        const float* __restrict__ bias, float* __restrict__ C,
                        int M, int N, int K, int T) {
    __shared__ float As[16*68];
    __shared__ float Bs[16*68];
    int tid = threadIdx.x;
    int tx = tid & 15, ty = tid >> 4;
    int m0 = blockIdx.y * 64, n0 = blockIdx.x * 64;
    float acc[4][4] = {};
    int ar = tid >> 2, ak = (tid & 3) * 4;
    int br = tid >> 4, bn = (tid & 15) * 4;

    for (int k0 = 0; k0 < K; k0 += 16) {
        float4 a = *(const float4*)(A + (size_t)(m0 + ar) * K + k0 + ak);
        As[(ak+0)*68 + ar] = a.x;
        As[(ak+1)*68 + ar] = a.y;
        As[(ak+2)*68 + ar] = a.z;
        As[(ak+3)*68 + ar] = a.w;
        *(float4*)(Bs + br*68 + bn) = *(const float4*)(W + (size_t)(k0 + br) * N + n0 + bn);
        __syncthreads();
        #pragma unroll
        for (int k = 0; k < 16; k++) {
            float4 av = *(const float4*)(As + k*68 + ty*4);
            float4 bv = *(const float4*)(Bs + k*68 + tx*4);
            float ax[4] = {av.x, av.y, av.z, av.w};
            float bx[4] = {bv.x, bv.y, bv.z, bv.w};
            #pragma unroll
            for (int r = 0; r < 4; r++)
                #pragma unroll
                for (int c = 0; c < 4; c++)
                    acc[r][c] += ax[r] * bx[c];
        }
        __syncthreads();
    }

    int col = n0 + tx*4;
    float4 bv4 = *(const float4*)(bias + col);
    float bz[4] = {bv4.x, bv4.y, bv4.z, bv4.w};
    #pragma unroll
    for (int r = 0; r < 4; r++) {
        int row = m0 + ty*4 + r;
        float vals[4];
        #pragma unroll
        for (int c = 0; c < 4; c++) {
            float v = acc[r][c] + bz[c];
            if (MODE == 2) v = 0.5f * v * (1.f + erff(v * 0.70710678118654752f));
            vals[c] = v;
        }
        float4 o = make_float4(vals[0], vals[1], vals[2], vals[3]);
        if (MODE == 1) {
            int bidx = row / T, t = row % T;
            int h = col >> 6, d = col & 63;
            *(float4*)(C + (size_t)((bidx*HH + h)*T + t)*HD + d) = o;
        } else {
            *(float4*)(C + (size_t)row * N + col) = o;
        }
    }
}

// ---------------- attention pass A: logits + online (m, Z) ----------------
// grid: (S/64, B*H), 256 threads. Writes raw logits into the attn output region.
__global__ void attn_scores_kernel(const float* __restrict__ q, const float* __restrict__ k,
                                   const float* __restrict__ shead, const float* __restrict__ ep_b,
                                   float* __restrict__ logits,
                                   float* __restrict__ gm, float* __restrict__ gz) {
    __shared__ float qs[64*68];
    __shared__ float ks[64*68];
    __shared__ float sm_m[64], sm_l[64];
    int tid = threadIdx.x;
    int tx = tid & 15, ty = tid >> 4;
    int bh = blockIdx.y;
    int i0 = blockIdx.x * 64;
    const float* qb = q + ((size_t)bh * SS + i0) * HD;
    const float* kb = k + (size_t)bh * PP * HD;
    float* lb = logits + ((size_t)bh * SS + i0) * PP;
    float sh_scale = shead[bh & (HH-1)];
    float epb = ep_b[0];

    // load q tile transposed: qs[d][i]
    #pragma unroll
    for (int rr = 0; rr < 4; rr++) {
        int i = (tid >> 4) + rr*16;
        int d4 = (tid & 15) * 4;
        float4 v = *(const float4*)(qb + (size_t)i*HD + d4);
        qs[(d4+0)*68 + i] = v.x;
        qs[(d4+1)*68 + i] = v.y;
        qs[(d4+2)*68 + i] = v.z;
        qs[(d4+3)*68 + i] = v.w;
    }
    if (tid < 64) { sm_m[tid] = -INFINITY; sm_l[tid] = 0.f; }
    __syncthreads();

    for (int j0 = 0; j0 < PP; j0 += 64) {
        // load k tile transposed: ks[d][j]
        #pragma unroll
        for (int rr = 0; rr < 4; rr++) {
            int j = (tid >> 4) + rr*16;
            int d4 = (tid & 15) * 4;
            float4 v = *(const float4*)(kb + (size_t)(j0 + j)*HD + d4);
            ks[(d4+0)*68 + j] = v.x;
            ks[(d4+1)*68 + j] = v.y;
            ks[(d4+2)*68 + j] = v.z;
            ks[(d4+3)*68 + j] = v.w;
        }
        __syncthreads();

        float acc[4][4] = {};
        #pragma unroll 16
        for (int d = 0; d < 64; d++) {
            float4 av = *(const float4*)(qs + d*68 + ty*4);
            float4 bv = *(const float4*)(ks + d*68 + tx*4);
            float ax[4] = {av.x, av.y, av.z, av.w};
            float bx[4] = {bv.x, bv.y, bv.z, bv.w};
            #pragma unroll
            for (int r = 0; r < 4; r++)
                #pragma unroll
                for (int c = 0; c < 4; c++)
                    acc[r][c] += ax[r] * bx[c];
        }

        // scores -> logits (edge score fused), store raw logits
        #pragma unroll
        for (int r = 0; r < 4; r++) {
            #pragma unroll
            for (int c = 0; c < 4; c++) {
                float sc = acc[r][c] * 0.125f;                 // HD^-0.5
                float t = sc * sh_scale + epb;
                float e = t > 0.f ? t : 0.2f * t;              // leaky_relu(0.2)
                acc[r][c] = sc + e;
            }
            int iloc = ty*4 + r;
            *(float4*)(lb + (size_t)iloc*PP + j0 + tx*4) =
                make_float4(acc[r][0], acc[r][1], acc[r][2], acc[r][3]);
        }

        // per-row online softmax stats (16 threads per row-group, shfl over tx)
        #pragma unroll
        for (int r = 0; r < 4; r++) {
            int iloc = ty*4 + r;
            float tm = fmaxf(fmaxf(acc[r][0], acc[r][1]), fmaxf(acc[r][2], acc[r][3]));
            #pragma unroll
            for (int o = 8; o; o >>= 1) tm = fmaxf(tm, __shfl_xor_sync(0xffffffffu, tm, o));
            float mo = sm_m[iloc];
            float nm = fmaxf(mo, tm);
            float pe = expf(acc[r][0]-nm) + expf(acc[r][1]-nm)
                     + expf(acc[r][2]-nm) + expf(acc[r][3]-nm);
            #pragma unroll
            for (int o = 8; o; o >>= 1) pe += __shfl_xor_sync(0xffffffffu, pe, o);
            if (tx == 0) {
                sm_m[iloc] = nm;
                sm_l[iloc] = sm_l[iloc] * expf(mo - nm) + pe;
            }
        }
        __syncthreads();
    }

    if (tid < 64) {
        gm[(size_t)bh*SS + i0 + tid] = sm_m[tid];
        gz[(size_t)bh*SS + i0 + tid] = sm_l[tid];
    }
}

// ---------------- attention pass B: normalize attn in place + P @ V ----------------
__global__ void attn_pv_kernel(const float* __restrict__ v,
                               const float* __restrict__ gm, const float* __restrict__ gz,
                               float* __restrict__ attn, float* __restrict__ out) {
    __shared__ float ps[64*68];
    __shared__ float vs[64*68];
    __shared__ float sm_m[64], sm_iz[64];
    int tid = threadIdx.x;
    int tx = tid & 15, ty = tid >> 4;
    int bh = blockIdx.y;
    int b = bh >> 3, h = bh & 7;
    int i0 = blockIdx.x * 64;
    float* ab = attn + ((size_t)bh * SS + i0) * PP;
    const float* vb = v + (size_t)bh * PP * HD;

    if (tid < 64) {
        sm_m[tid]  = gm[(size_t)bh*SS + i0 + tid];
        sm_iz[tid] = 1.f / gz[(size_t)bh*SS + i0 + tid];
    }
    __syncthreads();

    float acc[4][4] = {};
    for (int j0 = 0; j0 < PP; j0 += 64) {
        #pragma unroll
        for (int rr = 0; rr < 4; rr++) {
            int i = (tid >> 4) + rr*16;
            int j4 = (tid & 15) * 4;
            float4 lv = *(const float4*)(ab + (size_t)i*PP + j0 + j4);
            float m = sm_m[i], iz = sm_iz[i];
            float p0 = expf(lv.x - m) * iz;
            float p1 = expf(lv.y - m) * iz;
            float p2 = expf(lv.z - m) * iz;
            float p3 = expf(lv.w - m) * iz;
            *(float4*)(ab + (size_t)i*PP + j0 + j4) = make_float4(p0, p1, p2, p3);
            ps[(j4+0)*68 + i] = p0;
            ps[(j4+1)*68 + i] = p1;
            ps[(j4+2)*68 + i] = p2;
            ps[(j4+3)*68 + i] = p3;
            // v tile: vs[j][d]
            int j = i, d4 = j4;
            *(float4*)(vs + j*68 + d4) = *(const float4*)(vb + (size_t)(j0 + j)*HD + d4);
        }
        __syncthreads();
        #pragma unroll 16
        for (int jj = 0; jj < 64; jj++) {
            float4 av = *(const float4*)(ps + jj*68 + ty*4);
            float4 bv = *(const float4*)(vs + jj*68 + tx*4);
            float ax[4] = {av.x, av.y, av.z, av.w};
            float bx[4] = {bv.x, bv.y, bv.z, bv.w};
            #pragma unroll
            for (int r = 0; r < 4; r++)
                #pragma unroll
                for (int c = 0; c < 4; c++)
                    acc[r][c] += ax[r] * bx[c];
        }
        __syncthreads();
    }

    // out[b, i, h*64+d]
    #pragma unroll
    for (int r = 0; r < 4; r++) {
        int row = (b*SS + i0 + ty*4 + r);
        *(float4*)(out + (size_t)row*TD + h*HD + tx*4) =
            make_float4(acc[r][0], acc[r][1], acc[r][2], acc[r][3]);
    }
}

// ---------------- launch ----------------
extern "C" void kernel_launch(void* const* d_in, const int* in_sizes, int n_in,
                              void* d_out, int out_size) {
    const float* text  = (const float*)d_in[0];
    const float* shape = (const float*)d_in[1];
    const float* tn_g = (const float*)d_in[2];
    const float* tn_b = (const float*)d_in[3];
    const float* sn_g = (const float*)d_in[4];
    const float* sn_b = (const float*)d_in[5];
    const float* Wq = (const float*)d_in[6];
    const float* bq = (const float*)d_in[7];
    const float* Wk = (const float*)d_in[8];
    const float* bk = (const float*)d_in[9];
    const float* Wv = (const float*)d_in[10];
    const float* bv = (const float*)d_in[11];
    const float* edge_emb = (const float*)d_in[12];
    const float* ep_w = (const float*)d_in[13];
    const float* ep_b = (const float*)d_in[14];
    const float* Wo = (const float*)d_in[15];
    const float* bo = (const float*)d_in[16];
    const float* on_g = (const float*)d_in[17];
    const float* on_b = (const float*)d_in[18];
    const float* W1 = (const float*)d_in[19];
    const float* b1 = (const float*)d_in[20];
    const float* W2 = (const float*)d_in[21];
    const float* b2 = (const float*)d_in[22];
    const float* fn_g = (const float*)d_in[23];
    const float* fn_b = (const float*)d_in[24];

    float* out_final = (float*)d_out;                 // [2,512,512]
    float* attn_buf  = (float*)d_out + OUT_ELEMS;     // [2,8,512,4096]

    float *p_tn, *p_sn, *p_q, *p_k, *p_v, *p_m, *p_z, *p_ao, *p_o1, *p_hid, *p_tmp, *p_sh;
    cudaGetSymbolAddress((void**)&p_tn, g_tn);
    cudaGetSymbolAddress((void**)&p_sn, g_sn);
    cudaGetSymbolAddress((void**)&p_q,  g_q);
    cudaGetSymbolAddress((void**)&p_k,  g_k);
    cudaGetSymbolAddress((void**)&p_v,  g_v);
    cudaGetSymbolAddress((void**)&p_m,  g_m);
    cudaGetSymbolAddress((void**)&p_z,  g_z);
    cudaGetSymbolAddress((void**)&p_ao, g_attnout);
    cudaGetSymbolAddress((void**)&p_o1, g_out1);
    cudaGetSymbolAddress((void**)&p_hid, g_hid);
    cudaGetSymbolAddress((void**)&p_tmp, g_tmp);
    cudaGetSymbolAddress((void**)&p_sh, g_shead);

    // 1. LayerNorms of inputs
    ln_kernel<<<NROW_T, 128>>>(text, nullptr, tn_g, tn_b, p_tn, TD);
    ln_kernel<<<NROW_S, 128>>>(shape, nullptr, sn_g, sn_b, p_sn, SD);
    edge_scalar_kernel<<<1, 32>>>(edge_emb, ep_w, p_sh);

    // 2. Q/K/V projections (scatter to [b,h,t,d])
    sgemm64<1><<<dim3(TD/64, NROW_T/64), 256>>>(p_tn, Wq, bq, p_q, NROW_T, TD, TD, SS);
    sgemm64<1><<<dim3(TD/64, NROW_S/64), 256>>>(p_sn, Wk, bk, p_k, NROW_S, TD, SD, PP);
    sgemm64<1><<<dim3(TD/64, NROW_S/64), 256>>>(p_sn, Wv, bv, p_v, NROW_S, TD, SD, PP);

    // 3. attention
    attn_scores_kernel<<<dim3(SS/64, BB*HH), 256>>>(p_q, p_k, p_sh, ep_b, attn_buf, p_m, p_z);
    attn_pv_kernel<<<dim3(SS/64, BB*HH), 256>>>(p_v, p_m, p_z, attn_buf, p_ao);

    // 4. output proj + residual + LN
    sgemm64<0><<<dim3(TD/64, NROW_T/64), 256>>>(p_ao, Wo, bo, p_tmp, NROW_T, TD, TD, 0);
    ln_kernel<<<NROW_T, 128>>>(text, p_tmp, on_g, on_b, p_o1, TD);

    // 5. FFN + residual + LN
    sgemm64<2><<<dim3(FF/64, NROW_T/64), 256>>>(p_o1, W1, b1, p_hid, NROW_T, FF, TD, 0);
    sgemm64<0><<<dim3(TD/64, NROW_T/64), 256>>>(p_hid, W2, b2, p_tmp, NROW_T, TD, FF, 0);
    ln_kernel<<<NROW_T, 128>>>(p_o1, p_tmp, fn_g, fn_b, out_final, TD);
}